// round 2
// baseline (speedup 1.0000x reference)
#include <cuda_runtime.h>
#include <math.h>

#define NN 20000
#define NE 200000

__device__ float g_hA[NN * 32 * 13];
__device__ float g_hB[NN * 32 * 13];
__device__ float g_tx1[NN * 384];
__device__ float g_skip[NN * 256];
__device__ float g_y[NN * 512];
__device__ float g_means[NN];
__device__ float g_stdev[NN];
__device__ float g_dinv[NN];
__device__ float g_norme[NE];
__device__ float g_bn[8 * 64];

__device__ __forceinline__ float ftanh(float x) {
    x = fminf(fmaxf(x, -15.f), 15.f);
    float e = __expf(2.f * x);
    return __fdividef(e - 1.f, e + 1.f);
}
__device__ __forceinline__ float fsig(float x) {
    x = fminf(fmaxf(x, -30.f), 30.f);
    return __fdividef(1.f, 1.f + __expf(-x));
}

__global__ void zero_prep() {
    int i = blockIdx.x * blockDim.x + threadIdx.x;
    if (i < 512) g_bn[i] = 0.f;
    if (i < NN) g_dinv[i] = 0.f;
}
__global__ void zero_tx1(int n) {
    int i = blockIdx.x * blockDim.x + threadIdx.x;
    if (i < n) g_tx1[i] = 0.f;
}
__global__ void deg_kernel(const int* __restrict__ ei, const float* __restrict__ ea) {
    int e = blockIdx.x * blockDim.x + threadIdx.x;
    if (e >= NE) return;
    int r = ei[e], c = ei[NE + e];
    float w = (r == c) ? 0.f : ea[e];
    if (w != 0.f) atomicAdd(&g_dinv[r], w);
}
__global__ void dinv_kernel() {
    int n = blockIdx.x * blockDim.x + threadIdx.x;
    if (n >= NN) return;
    float d = g_dinv[n];
    g_dinv[n] = (d > 0.f) ? rsqrtf(d) : 0.f;
}
__global__ void norme_kernel(const int* __restrict__ ei, const float* __restrict__ ea) {
    int e = blockIdx.x * blockDim.x + threadIdx.x;
    if (e >= NE) return;
    int r = ei[e], c = ei[NE + e];
    float w = (r == c) ? 0.f : ea[e];
    g_norme[e] = g_dinv[r] * w * g_dinv[c];
}

// instance norm over T + 1x1 start conv -> g_hA [N,32,13]
__global__ void instnorm_start(const float* __restrict__ x,
                               const float* __restrict__ sW,
                               const float* __restrict__ sb) {
    int gw = blockIdx.x * 8 + (threadIdx.x >> 5);
    int lane = threadIdx.x & 31;
    if (gw >= NN) return;
    float v = (lane < 13) ? x[gw * 13 + lane] : 0.f;
    float s = v;
    #pragma unroll
    for (int o = 16; o; o >>= 1) s += __shfl_xor_sync(0xffffffffu, s, o);
    float mean = s * (1.f / 13.f);
    float xc = (lane < 13) ? (v - mean) : 0.f;
    float q = xc * xc;
    #pragma unroll
    for (int o = 16; o; o >>= 1) q += __shfl_xor_sync(0xffffffffu, q, o);
    float sd = sqrtf(q * (1.f / 13.f) + 1e-5f);
    if (lane == 0) { g_means[gw] = mean; g_stdev[gw] = sd; }
    float nv = xc * __fdividef(1.f, sd);
    float w = sW[lane], b = sb[lane];
    float* hr = g_hA + (gw * 32 + lane) * 13;
    #pragma unroll
    for (int t = 0; t < 13; t++)
        hr[t] = w * __shfl_sync(0xffffffffu, nv, t) + b;
}

// fused: dilated conv (filter,gate) + tanh*sigmoid + residual + BN stats
template <int L, int TIN, int TOUT, int DIL>
__global__ void conv_kernel(const float* __restrict__ X, float* __restrict__ Y,
                            const float* __restrict__ fW, const float* __restrict__ fB,
                            const float* __restrict__ gW, const float* __restrict__ gB) {
    __shared__ float wf0[32 * 33], wf1[32 * 33], wg0[32 * 33], wg1[32 * 33];
    __shared__ float bfs[32], bgs[32];
    __shared__ float hs[8][32 * 13];
    __shared__ float bnred[64];
    int tid = threadIdx.x;
    for (int i = tid; i < 1024; i += 256) {
        int c = i & 31, o = i >> 5;
        int gbase = (L * 32 + o) * 64 + c * 2;
        wf0[c * 33 + o] = fW[gbase + 0];
        wf1[c * 33 + o] = fW[gbase + 1];
        wg0[c * 33 + o] = gW[gbase + 0];
        wg1[c * 33 + o] = gW[gbase + 1];
    }
    if (tid < 32) { bfs[tid] = fB[L * 32 + tid]; bgs[tid] = gB[L * 32 + tid]; }
    if (tid < 64) bnred[tid] = 0.f;
    __syncthreads();

    int warp = tid >> 5, lane = tid & 31;
    int gw = blockIdx.x * 8 + warp;
    int nwarp = gridDim.x * 8;
    float bsum = 0.f, bsq = 0.f;
    float* hwp = &hs[warp][0];

    for (int n = gw; n < NN; n += nwarp) {
        const float* xr = X + (n * 32 + lane) * TIN;
        float* hrow = hwp + lane * TIN;
        #pragma unroll
        for (int t = 0; t < TIN; t++) hrow[t] = xr[t];
        __syncwarp();

        float accf[TOUT], accg[TOUT];
        #pragma unroll
        for (int t = 0; t < TOUT; t++) { accf[t] = bfs[lane]; accg[t] = bgs[lane]; }

        #pragma unroll 4
        for (int c = 0; c < 32; c++) {
            float w00 = wf0[c * 33 + lane], w01 = wf1[c * 33 + lane];
            float w10 = wg0[c * 33 + lane], w11 = wg1[c * 33 + lane];
            const float* hv = hwp + c * TIN;
            float hvr[TIN];
            #pragma unroll
            for (int t = 0; t < TIN; t++) hvr[t] = hv[t];
            #pragma unroll
            for (int t = 0; t < TOUT; t++) {
                accf[t] += w00 * hvr[t] + w01 * hvr[t + DIL];
                accg[t] += w10 * hvr[t] + w11 * hvr[t + DIL];
            }
        }
        float* yr = Y + (n * 32 + lane) * TOUT;
        #pragma unroll
        for (int t = 0; t < TOUT; t++) {
            float f = ftanh(accf[t]);
            float g = fsig(accg[t]);
            float ho = f * g + hwp[lane * TIN + t + DIL];
            yr[t] = ho;
            bsum += ho; bsq += ho * ho;
        }
        __syncwarp();
    }
    atomicAdd(&bnred[lane], bsum);
    atomicAdd(&bnred[32 + lane], bsq);
    __syncthreads();
    if (tid < 64) atomicAdd(&g_bn[L * 64 + tid], bnred[tid]);
}

// skip += skip_W[L] @ (Y_last - X_last) + skip_b[L]   (last time column only)
template <int L, bool FIRST, int TIN, int TOUT>
__global__ void skip_kernel(const float* __restrict__ X, const float* __restrict__ Y,
                            const float* __restrict__ sW, const float* __restrict__ sB) {
    __shared__ float sws[32 * 257];
    __shared__ float sbs[256];
    int tid = threadIdx.x;
    for (int i = tid; i < 8192; i += 256) {
        int c = i & 31, o = i >> 5;
        sws[c * 257 + o] = sW[L * 8192 + o * 32 + c];
    }
    if (tid < 256) sbs[tid] = sB[L * 256 + tid];
    __syncthreads();

    int warp = tid >> 5, lane = tid & 31;
    int gw = blockIdx.x * 8 + warp;
    int nwarp = gridDim.x * 8;
    for (int n = gw; n < NN; n += nwarp) {
        float hn = Y[(n * 32 + lane) * TOUT + (TOUT - 1)] - X[(n * 32 + lane) * TIN + (TIN - 1)];
        float acc[8];
        #pragma unroll
        for (int j = 0; j < 8; j++) acc[j] = sbs[lane + 32 * j];
        #pragma unroll 8
        for (int c = 0; c < 32; c++) {
            float h = __shfl_sync(0xffffffffu, hn, c);
            #pragma unroll
            for (int j = 0; j < 8; j++) acc[j] += sws[c * 257 + lane + 32 * j] * h;
        }
        float* sp = g_skip + n * 256;
        #pragma unroll
        for (int j = 0; j < 8; j++) {
            if (FIRST) sp[lane + 32 * j] = acc[j];
            else       sp[lane + 32 * j] += acc[j];
        }
    }
}

template <int L, int TOUT>
__global__ void bn_kernel(float* __restrict__ Y) {
    int idx = blockIdx.x * blockDim.x + threadIdx.x;
    if (idx >= NN * 32 * TOUT) return;
    int c = (idx / TOUT) & 31;
    const float cnt = (float)(NN * TOUT);
    float m = g_bn[L * 64 + c] / cnt;
    float var = g_bn[L * 64 + 32 + c] / cnt - m * m;
    Y[idx] = (Y[idx] - m) * rsqrtf(var + 1e-5f);
}

// tx1[col] -= norm * xf[row]
template <int F>
__global__ void scatter_kernel(const int* __restrict__ ei, const float* __restrict__ xf) {
    const int CH = F / 4;
    long gid = (long)blockIdx.x * blockDim.x + threadIdx.x;
    if (gid >= (long)NE * CH) return;
    int e = (int)(gid / CH);
    int q = (int)(gid - (long)e * CH);
    float nrm = g_norme[e];
    if (nrm == 0.f) return;
    int r = ei[e], c = ei[NE + e];
    float4 v = *(const float4*)(xf + (long)r * F + q * 4);
    float* dst = g_tx1 + (long)c * F + q * 4;
    atomicAdd(dst + 0, -nrm * v.x);
    atomicAdd(dst + 1, -nrm * v.y);
    atomicAdd(dst + 2, -nrm * v.z);
    atomicAdd(dst + 3, -nrm * v.w);
}

// C = A1@B1 + A2@B2 + bias  ; 64x64 tiles
template <int F>
__global__ void cheb_gemm(const float* __restrict__ A1, const float* __restrict__ A2,
                          const float* __restrict__ B1, const float* __restrict__ B2,
                          const float* __restrict__ bias, float* __restrict__ C) {
    __shared__ float As1[16 * 65], As2[16 * 65];
    __shared__ float Bs1[16 * 64], Bs2[16 * 64];
    int tid = threadIdx.x;
    int bm = blockIdx.x * 64, bn = blockIdx.y * 64;
    int tx = tid & 15, ty = tid >> 4;
    int ka = tid & 15, ma0 = tid >> 4;
    int jb = tid & 63, kb0 = tid >> 6;
    float acc[4][4];
    #pragma unroll
    for (int i = 0; i < 4; i++)
        #pragma unroll
        for (int j = 0; j < 4; j++) acc[i][j] = 0.f;

    for (int k0 = 0; k0 < F; k0 += 16) {
        #pragma unroll
        for (int r = 0; r < 4; r++) {
            int m = ma0 + r * 16;
            int row = bm + m;
            float a1 = 0.f, a2 = 0.f;
            if (row < NN) {
                a1 = A1[(long)row * F + k0 + ka];
                a2 = A2[(long)row * F + k0 + ka];
            }
            As1[ka * 65 + m] = a1;
            As2[ka * 65 + m] = a2;
            int kk = kb0 + r * 4;
            Bs1[kk * 64 + jb] = B1[(long)(k0 + kk) * F + bn + jb];
            Bs2[kk * 64 + jb] = B2[(long)(k0 + kk) * F + bn + jb];
        }
        __syncthreads();
        #pragma unroll
        for (int k = 0; k < 16; k++) {
            float4 b1 = *(const float4*)&Bs1[k * 64 + tx * 4];
            float4 b2 = *(const float4*)&Bs2[k * 64 + tx * 4];
            #pragma unroll
            for (int i = 0; i < 4; i++) {
                float a1 = As1[k * 65 + ty * 4 + i];
                float a2 = As2[k * 65 + ty * 4 + i];
                acc[i][0] += a1 * b1.x + a2 * b2.x;
                acc[i][1] += a1 * b1.y + a2 * b2.y;
                acc[i][2] += a1 * b1.z + a2 * b2.z;
                acc[i][3] += a1 * b1.w + a2 * b2.w;
            }
        }
        __syncthreads();
    }
    float4 bv = *(const float4*)&bias[bn + tx * 4];
    #pragma unroll
    for (int i = 0; i < 4; i++) {
        int row = bm + ty * 4 + i;
        if (row < NN) {
            float4 o;
            o.x = acc[i][0] + bv.x; o.y = acc[i][1] + bv.y;
            o.z = acc[i][2] + bv.z; o.w = acc[i][3] + bv.w;
            *(float4*)&C[(long)row * F + bn + tx * 4] = o;
        }
    }
}

// g_y = relu(g_skip) @ W^T + b ; W [512,256]
__global__ void end1_gemm(const float* __restrict__ W, const float* __restrict__ bias) {
    const int K = 256;
    __shared__ float As[16 * 65], Bs[16 * 65];
    int tid = threadIdx.x;
    int bm = blockIdx.x * 64, bn = blockIdx.y * 64;
    int tx = tid & 15, ty = tid >> 4;
    int ka = tid & 15, i0 = tid >> 4;
    float acc[4][4];
    #pragma unroll
    for (int i = 0; i < 4; i++)
        #pragma unroll
        for (int j = 0; j < 4; j++) acc[i][j] = 0.f;

    for (int k0 = 0; k0 < K; k0 += 16) {
        #pragma unroll
        for (int r = 0; r < 4; r++) {
            int m = i0 + r * 16;
            int row = bm + m;
            float a = 0.f;
            if (row < NN) a = fmaxf(g_skip[(long)row * K + k0 + ka], 0.f);
            As[ka * 65 + m] = a;
            int j = i0 + r * 16;
            Bs[ka * 65 + j] = W[(long)(bn + j) * K + k0 + ka];
        }
        __syncthreads();
        #pragma unroll
        for (int k = 0; k < 16; k++) {
            float b[4];
            #pragma unroll
            for (int j = 0; j < 4; j++) b[j] = Bs[k * 65 + tx * 4 + j];
            #pragma unroll
            for (int i = 0; i < 4; i++) {
                float a = As[k * 65 + ty * 4 + i];
                #pragma unroll
                for (int j = 0; j < 4; j++) acc[i][j] += a * b[j];
            }
        }
        __syncthreads();
    }
    #pragma unroll
    for (int i = 0; i < 4; i++) {
        int row = bm + ty * 4 + i;
        if (row < NN) {
            #pragma unroll
            for (int j = 0; j < 4; j++)
                g_y[(long)row * 512 + bn + tx * 4 + j] = acc[i][j] + bias[bn + tx * 4 + j];
        }
    }
}

// out = (g_y @ W2^T + b2) * stdev + means ; W2 [12,512]
__global__ void end2_final(const float* __restrict__ W, const float* __restrict__ bias,
                           float* __restrict__ out) {
    __shared__ float ws[512 * 12];
    __shared__ float bs[12];
    int tid = threadIdx.x;
    for (int i = tid; i < 6144; i += 256) {
        int c = i & 511, h = i >> 9;
        ws[c * 12 + h] = W[h * 512 + c];
    }
    if (tid < 12) bs[tid] = bias[tid];
    __syncthreads();

    int warp = tid >> 5, lane = tid & 31;
    int gw = blockIdx.x * 8 + warp;
    int nwarp = gridDim.x * 8;
    for (int n = gw; n < NN; n += nwarp) {
        float acc[12];
        #pragma unroll
        for (int h = 0; h < 12; h++) acc[h] = 0.f;
        #pragma unroll 4
        for (int i = 0; i < 16; i++) {
            int c = lane + 32 * i;
            float yv = g_y[(long)n * 512 + c];
            #pragma unroll
            for (int h = 0; h < 12; h++) acc[h] += yv * ws[c * 12 + h];
        }
        #pragma unroll
        for (int h = 0; h < 12; h++) {
            #pragma unroll
            for (int off = 16; off; off >>= 1)
                acc[h] += __shfl_down_sync(0xffffffffu, acc[h], off);
        }
        if (lane == 0) {
            float sd = g_stdev[n], mn = g_means[n];
            #pragma unroll
            for (int h = 0; h < 12; h++)
                out[n * 12 + h] = (acc[h] + bs[h]) * sd + mn;
        }
    }
}

extern "C" void kernel_launch(void* const* d_in, const int* in_sizes, int n_in,
                              void* d_out, int out_size) {
    (void)in_sizes; (void)n_in; (void)out_size;
    const float* x      = (const float*)d_in[0];
    const int*   ei     = (const int*)d_in[1];
    const float* ea     = (const float*)d_in[2];
    const float* startW = (const float*)d_in[3];
    const float* startb = (const float*)d_in[4];
    const float* fW     = (const float*)d_in[5];
    const float* fb     = (const float*)d_in[6];
    const float* gW     = (const float*)d_in[7];
    const float* gb     = (const float*)d_in[8];
    const float* sW     = (const float*)d_in[9];
    const float* sb     = (const float*)d_in[10];
    const float* g0W0   = (const float*)d_in[11];
    const float* g0W1   = (const float*)d_in[12];
    const float* g0b    = (const float*)d_in[13];
    const float* g1W0   = (const float*)d_in[14];
    const float* g1W1   = (const float*)d_in[15];
    const float* g1b    = (const float*)d_in[16];
    const float* e1W    = (const float*)d_in[17];
    const float* e1b    = (const float*)d_in[18];
    const float* e2W    = (const float*)d_in[19];
    const float* e2b    = (const float*)d_in[20];
    float* out = (float*)d_out;

    float *hA, *hB, *tx1;
    cudaGetSymbolAddress((void**)&hA, g_hA);
    cudaGetSymbolAddress((void**)&hB, g_hB);
    cudaGetSymbolAddress((void**)&tx1, g_tx1);

    zero_prep<<<(NN + 255) / 256, 256>>>();
    deg_kernel<<<(NE + 255) / 256, 256>>>(ei, ea);
    dinv_kernel<<<(NN + 255) / 256, 256>>>();
    norme_kernel<<<(NE + 255) / 256, 256>>>(ei, ea);
    instnorm_start<<<2500, 256>>>(x, startW, startb);

    // layer 0: 13 -> 12, d=1 (hA -> hB)
    conv_kernel<0, 13, 12, 1><<<625, 256>>>(hA, hB, fW, fb, gW, gb);
    skip_kernel<0, true, 13, 12><<<625, 256>>>(hA, hB, sW, sb);
    bn_kernel<0, 12><<<(NN * 32 * 12 + 255) / 256, 256>>>(hB);

    // GCN0 on [N,384] (hB -> hA)
    zero_tx1<<<(NN * 384 + 255) / 256, 256>>>(NN * 384);
    scatter_kernel<384><<<(NE * 96 + 255) / 256, 256>>>(ei, hB);
    cheb_gemm<384><<<dim3(313, 6), 256>>>(hB, tx1, g0W0, g0W1, g0b, hA);

    // layer 1: 12 -> 10, d=2 (hA -> hB)
    conv_kernel<1, 12, 10, 2><<<625, 256>>>(hA, hB, fW, fb, gW, gb);
    skip_kernel<1, false, 12, 10><<<625, 256>>>(hA, hB, sW, sb);
    bn_kernel<1, 10><<<(NN * 32 * 10 + 255) / 256, 256>>>(hB);

    // layer 2: 10 -> 9, d=1 (hB -> hA)
    conv_kernel<2, 10, 9, 1><<<625, 256>>>(hB, hA, fW, fb, gW, gb);
    skip_kernel<2, false, 10, 9><<<625, 256>>>(hB, hA, sW, sb);
    bn_kernel<2, 9><<<(NN * 32 * 9 + 255) / 256, 256>>>(hA);

    // layer 3: 9 -> 7, d=2 (hA -> hB)
    conv_kernel<3, 9, 7, 2><<<625, 256>>>(hA, hB, fW, fb, gW, gb);
    skip_kernel<3, false, 9, 7><<<625, 256>>>(hA, hB, sW, sb);
    bn_kernel<3, 7><<<(NN * 32 * 7 + 255) / 256, 256>>>(hB);

    // layer 4: 7 -> 6, d=1 (hB -> hA)
    conv_kernel<4, 7, 6, 1><<<625, 256>>>(hB, hA, fW, fb, gW, gb);
    skip_kernel<4, false, 7, 6><<<625, 256>>>(hB, hA, sW, sb);
    bn_kernel<4, 6><<<(NN * 32 * 6 + 255) / 256, 256>>>(hA);

    // GCN1 on [N,192] (hA -> hB)
    zero_tx1<<<(NN * 192 + 255) / 256, 256>>>(NN * 192);
    scatter_kernel<192><<<(NE * 48 + 255) / 256, 256>>>(ei, hA);
    cheb_gemm<192><<<dim3(313, 3), 256>>>(hA, tx1, g1W0, g1W1, g1b, hB);

    // layer 5: 6 -> 4, d=2 (hB -> hA)
    conv_kernel<5, 6, 4, 2><<<625, 256>>>(hB, hA, fW, fb, gW, gb);
    skip_kernel<5, false, 6, 4><<<625, 256>>>(hB, hA, sW, sb);
    bn_kernel<5, 4><<<(NN * 32 * 4 + 255) / 256, 256>>>(hA);

    // layer 6: 4 -> 3, d=1 (hA -> hB)
    conv_kernel<6, 4, 3, 1><<<625, 256>>>(hA, hB, fW, fb, gW, gb);
    skip_kernel<6, false, 4, 3><<<625, 256>>>(hA, hB, sW, sb);
    bn_kernel<6, 3><<<(NN * 32 * 3 + 255) / 256, 256>>>(hB);

    // layer 7: 3 -> 1, d=2 (hB -> hA); h is dead after, only skip matters
    conv_kernel<7, 3, 1, 2><<<625, 256>>>(hB, hA, fW, fb, gW, gb);
    skip_kernel<7, false, 3, 1><<<625, 256>>>(hB, hA, sW, sb);

    // head
    end1_gemm<<<dim3(313, 8), 256>>>(e1W, e1b);
    end2_final<<<2500, 256>>>(e2W, e2b, out);
}

// round 3
// speedup vs baseline: 1.2637x; 1.2637x over previous
#include <cuda_runtime.h>
#include <math.h>

#define NN 20000
#define NE 200000

__device__ float g_hA[NN * 32 * 13];
__device__ float g_hB[NN * 32 * 13];
__device__ float g_tx1[NN * 384];
__device__ float g_hlast[NN * 256];
__device__ float g_skip[NN * 256];
__device__ float g_y[NN * 512];
__device__ float g_means[NN];
__device__ float g_stdev[NN];
__device__ float g_dinv[NN];
__device__ float g_norme[NE];
__device__ float g_bn[8 * 64];
__device__ float g_bnp[2 * 64];   // finalized BN scale/shift for the two GCN points
__device__ float g_sbsum[256];

__device__ __forceinline__ float ftanh(float x) {
    x = fminf(fmaxf(x, -15.f), 15.f);
    float e = __expf(2.f * x);
    return __fdividef(e - 1.f, e + 1.f);
}
__device__ __forceinline__ float fsig(float x) {
    x = fminf(fmaxf(x, -30.f), 30.f);
    return __fdividef(1.f, 1.f + __expf(-x));
}

__global__ void zero_prep(const float* __restrict__ sB) {
    int i = blockIdx.x * blockDim.x + threadIdx.x;
    if (i < 512) g_bn[i] = 0.f;
    if (i < NN) g_dinv[i] = 0.f;
    if (i < 256) {
        float s = 0.f;
        #pragma unroll
        for (int l = 0; l < 8; l++) s += sB[l * 256 + i];
        g_sbsum[i] = s;
    }
}
__global__ void deg_kernel(const int* __restrict__ ei, const float* __restrict__ ea) {
    int e = blockIdx.x * blockDim.x + threadIdx.x;
    if (e >= NE) return;
    int r = ei[e], c = ei[NE + e];
    float w = (r == c) ? 0.f : ea[e];
    if (w != 0.f) atomicAdd(&g_dinv[r], w);
}
__global__ void dinv_kernel() {
    int n = blockIdx.x * blockDim.x + threadIdx.x;
    if (n >= NN) return;
    float d = g_dinv[n];
    g_dinv[n] = (d > 0.f) ? rsqrtf(d) : 0.f;
}
__global__ void norme_kernel(const int* __restrict__ ei, const float* __restrict__ ea) {
    int e = blockIdx.x * blockDim.x + threadIdx.x;
    if (e >= NE) return;
    int r = ei[e], c = ei[NE + e];
    float w = (r == c) ? 0.f : ea[e];
    g_norme[e] = -g_dinv[r] * w * g_dinv[c];   // pre-negated
}

// instance norm over T + 1x1 start conv -> g_hA [N,32,13]
__global__ void instnorm_start(const float* __restrict__ x,
                               const float* __restrict__ sW,
                               const float* __restrict__ sb) {
    int gw = blockIdx.x * 8 + (threadIdx.x >> 5);
    int lane = threadIdx.x & 31;
    if (gw >= NN) return;
    float v = (lane < 13) ? x[gw * 13 + lane] : 0.f;
    float s = v;
    #pragma unroll
    for (int o = 16; o; o >>= 1) s += __shfl_xor_sync(0xffffffffu, s, o);
    float mean = s * (1.f / 13.f);
    float xc = (lane < 13) ? (v - mean) : 0.f;
    float q = xc * xc;
    #pragma unroll
    for (int o = 16; o; o >>= 1) q += __shfl_xor_sync(0xffffffffu, q, o);
    float sd = sqrtf(q * (1.f / 13.f) + 1e-5f);
    if (lane == 0) { g_means[gw] = mean; g_stdev[gw] = sd; }
    float nv = xc * __fdividef(1.f, sd);
    float w = sW[lane], b = sb[lane];
    float* hr = g_hA + (gw * 32 + lane) * 13;
    #pragma unroll
    for (int t = 0; t < 13; t++)
        hr[t] = w * __shfl_sync(0xffffffffu, nv, t) + b;
}

// fused: [BN-fold of prev layer on load] + dilated conv (filter,gate) + tanh*sig
// + residual + BN stats + hlast capture. PREVL<0 => no fold. WRITE_Y=false => layer 7.
template <int L, int TIN, int TOUT, int DIL, int PREVL, bool WRITE_Y>
__global__ void conv_kernel(const float* __restrict__ X, float* __restrict__ Y,
                            const float* __restrict__ fW, const float* __restrict__ fB,
                            const float* __restrict__ gW, const float* __restrict__ gB) {
    __shared__ float wf0[32 * 33], wf1[32 * 33], wg0[32 * 33], wg1[32 * 33];
    __shared__ float bfs[32], bgs[32];
    __shared__ float bsc[32], bsh[32];
    __shared__ float hs[8][32 * TIN];
    __shared__ float bnred[64];
    int tid = threadIdx.x;
    for (int i = tid; i < 1024; i += 256) {
        int c = i & 31, o = i >> 5;
        int gbase = (L * 32 + o) * 64 + c * 2;
        wf0[c * 33 + o] = fW[gbase + 0];
        wf1[c * 33 + o] = fW[gbase + 1];
        wg0[c * 33 + o] = gW[gbase + 0];
        wg1[c * 33 + o] = gW[gbase + 1];
    }
    if (tid < 32) {
        bfs[tid] = fB[L * 32 + tid]; bgs[tid] = gB[L * 32 + tid];
        if (PREVL >= 0) {
            const float cnt = (float)NN * (float)TIN;
            float m = g_bn[PREVL * 64 + tid] / cnt;
            float var = fmaxf(g_bn[PREVL * 64 + 32 + tid] / cnt - m * m, 0.f);
            float s = rsqrtf(var + 1e-5f);
            bsc[tid] = s; bsh[tid] = -m * s;
        }
    }
    if (tid < 64) bnred[tid] = 0.f;
    __syncthreads();

    int warp = tid >> 5, lane = tid & 31;
    int gw = blockIdx.x * 8 + warp;
    int nwarp = gridDim.x * 8;
    float bsum = 0.f, bsq = 0.f;
    float* hwp = &hs[warp][0];

    for (int n = gw; n < NN; n += nwarp) {
        const float* xr = X + (n * 32 + lane) * TIN;
        float* hrow = hwp + lane * TIN;
        #pragma unroll
        for (int t = 0; t < TIN; t++) {
            float v = xr[t];
            if (PREVL >= 0) v = v * bsc[lane] + bsh[lane];
            hrow[t] = v;
        }
        __syncwarp();

        float accf[TOUT], accg[TOUT];
        #pragma unroll
        for (int t = 0; t < TOUT; t++) { accf[t] = bfs[lane]; accg[t] = bgs[lane]; }

        #pragma unroll 4
        for (int c = 0; c < 32; c++) {
            float w00 = wf0[c * 33 + lane], w01 = wf1[c * 33 + lane];
            float w10 = wg0[c * 33 + lane], w11 = wg1[c * 33 + lane];
            const float* hv = hwp + c * TIN;
            float hvr[TIN];
            #pragma unroll
            for (int t = 0; t < TIN; t++) hvr[t] = hv[t];
            #pragma unroll
            for (int t = 0; t < TOUT; t++) {
                accf[t] += w00 * hvr[t] + w01 * hvr[t + DIL];
                accg[t] += w10 * hvr[t] + w11 * hvr[t + DIL];
            }
        }
        float* yr = Y + (n * 32 + lane) * TOUT;
        #pragma unroll
        for (int t = 0; t < TOUT; t++) {
            float f = ftanh(accf[t]);
            float g = fsig(accg[t]);
            float hn = f * g;
            if (t == TOUT - 1) g_hlast[n * 256 + L * 32 + lane] = hn;
            if (WRITE_Y) {
                float ho = hn + hwp[lane * TIN + t + DIL];
                yr[t] = ho;
                bsum += ho; bsq += ho * ho;
            }
        }
        __syncwarp();
    }
    if (WRITE_Y) {
        atomicAdd(&bnred[lane], bsum);
        atomicAdd(&bnred[32 + lane], bsq);
        __syncthreads();
        if (tid < 64) atomicAdd(&g_bn[L * 64 + tid], bnred[tid]);
    }
}

// finalize BN of layer L into g_bnp[SLOT]
template <int L, int TOUT, int SLOT>
__global__ void bn_finalize() {
    int i = threadIdx.x;
    if (i >= 32) return;
    const float cnt = (float)NN * (float)TOUT;
    float m = g_bn[L * 64 + i] / cnt;
    float var = fmaxf(g_bn[L * 64 + 32 + i] / cnt - m * m, 0.f);
    float s = rsqrtf(var + 1e-5f);
    g_bnp[SLOT * 64 + i] = s;
    g_bnp[SLOT * 64 + 32 + i] = -m * s;
}

// tx1[col] += (-norm) * BNfold(xf[row])
template <int F, int TDIV, int SLOT>
__global__ void scatter_kernel(const int* __restrict__ ei, const float* __restrict__ xf) {
    const int CH = F / 4;
    long gid = (long)blockIdx.x * blockDim.x + threadIdx.x;
    if (gid >= (long)NE * CH) return;
    int e = (int)(gid / CH);
    int q = (int)(gid - (long)e * CH);
    float nrm = g_norme[e];
    if (nrm == 0.f) return;
    int r = ei[e], c = ei[NE + e];
    float4 v = *(const float4*)(xf + (long)r * F + q * 4);
    const float* bp = g_bnp + SLOT * 64;
    int k = q * 4;
    int c0 = k / TDIV, c1 = (k + 1) / TDIV, c2 = (k + 2) / TDIV, c3 = (k + 3) / TDIV;
    v.x = v.x * bp[c0] + bp[32 + c0];
    v.y = v.y * bp[c1] + bp[32 + c1];
    v.z = v.z * bp[c2] + bp[32 + c2];
    v.w = v.w * bp[c3] + bp[32 + c3];
    float* dst = g_tx1 + (long)c * F + q * 4;
    atomicAdd(dst + 0, nrm * v.x);
    atomicAdd(dst + 1, nrm * v.y);
    atomicAdd(dst + 2, nrm * v.z);
    atomicAdd(dst + 3, nrm * v.w);
}

// ===== GEMM family: BM=128 BN=64 BK=16, 256 threads, 8x4 per thread =====
#define GBM 128
#define GBN 64
#define GBK 16

// C = BNfold(A1)@B1 + A2@B2 + bias   (B row-major [F,F])
template <int F, int TDIV, int SLOT>
__global__ void __launch_bounds__(256) cheb_gemm2(
        const float* __restrict__ A1, const float* __restrict__ A2,
        const float* __restrict__ B1, const float* __restrict__ B2,
        const float* __restrict__ bias, float* __restrict__ C) {
    __shared__ float As1[GBK][GBM + 4], As2[GBK][GBM + 4];
    __shared__ float Bs1[GBK][GBN], Bs2[GBK][GBN];
    __shared__ float bsc[32], bsh[32];
    int tid = threadIdx.x;
    if (tid < 32) { bsc[tid] = g_bnp[SLOT * 64 + tid]; bsh[tid] = g_bnp[SLOT * 64 + 32 + tid]; }
    __syncthreads();
    int bm = blockIdx.x * GBM, bn = blockIdx.y * GBN;
    int ty = tid >> 4, tx = tid & 15;
    float acc[8][4];
    #pragma unroll
    for (int i = 0; i < 8; i++)
        #pragma unroll
        for (int j = 0; j < 4; j++) acc[i][j] = 0.f;

    for (int k0 = 0; k0 < F; k0 += GBK) {
        #pragma unroll
        for (int qi = 0; qi < 2; qi++) {
            int q = tid + qi * 256;
            int row = q >> 2;
            int kq = (q & 3) * 4;
            int grow = bm + row;
            float4 a1 = make_float4(0.f, 0.f, 0.f, 0.f), a2 = a1;
            if (grow < NN) {
                a1 = *(const float4*)(A1 + (size_t)grow * F + k0 + kq);
                a2 = *(const float4*)(A2 + (size_t)grow * F + k0 + kq);
            }
            int k = k0 + kq;
            int c0 = k / TDIV, c1 = (k + 1) / TDIV, c2 = (k + 2) / TDIV, c3 = (k + 3) / TDIV;
            a1.x = a1.x * bsc[c0] + bsh[c0];
            a1.y = a1.y * bsc[c1] + bsh[c1];
            a1.z = a1.z * bsc[c2] + bsh[c2];
            a1.w = a1.w * bsc[c3] + bsh[c3];
            As1[kq + 0][row] = a1.x; As1[kq + 1][row] = a1.y;
            As1[kq + 2][row] = a1.z; As1[kq + 3][row] = a1.w;
            As2[kq + 0][row] = a2.x; As2[kq + 1][row] = a2.y;
            As2[kq + 2][row] = a2.z; As2[kq + 3][row] = a2.w;
        }
        {
            int kk = tid >> 4;
            int jb = (tid & 15) * 4;
            *(float4*)&Bs1[kk][jb] = *(const float4*)(B1 + (size_t)(k0 + kk) * F + bn + jb);
            *(float4*)&Bs2[kk][jb] = *(const float4*)(B2 + (size_t)(k0 + kk) * F + bn + jb);
        }
        __syncthreads();
        #pragma unroll
        for (int k = 0; k < GBK; k++) {
            float4 a1lo = *(float4*)&As1[k][ty * 8];
            float4 a1hi = *(float4*)&As1[k][ty * 8 + 4];
            float4 a2lo = *(float4*)&As2[k][ty * 8];
            float4 a2hi = *(float4*)&As2[k][ty * 8 + 4];
            float4 b1 = *(float4*)&Bs1[k][tx * 4];
            float4 b2 = *(float4*)&Bs2[k][tx * 4];
            float a1v[8] = {a1lo.x, a1lo.y, a1lo.z, a1lo.w, a1hi.x, a1hi.y, a1hi.z, a1hi.w};
            float a2v[8] = {a2lo.x, a2lo.y, a2lo.z, a2lo.w, a2hi.x, a2hi.y, a2hi.z, a2hi.w};
            float b1v[4] = {b1.x, b1.y, b1.z, b1.w};
            float b2v[4] = {b2.x, b2.y, b2.z, b2.w};
            #pragma unroll
            for (int i = 0; i < 8; i++)
                #pragma unroll
                for (int j = 0; j < 4; j++)
                    acc[i][j] += a1v[i] * b1v[j] + a2v[i] * b2v[j];
        }
        __syncthreads();
    }
    float4 bv = *(const float4*)&bias[bn + tx * 4];
    #pragma unroll
    for (int i = 0; i < 8; i++) {
        int grow = bm + ty * 8 + i;
        if (grow < NN) {
            float4 o;
            o.x = acc[i][0] + bv.x; o.y = acc[i][1] + bv.y;
            o.z = acc[i][2] + bv.z; o.w = acc[i][3] + bv.w;
            *(float4*)&C[(size_t)grow * F + bn + tx * 4] = o;
        }
    }
}

// g_skip = relu( g_hlast[N,256] @ Wcat^T + sbsum ), Wcat^T[o][k] = sW[(k>>5)*8192 + o*32 + (k&31)]
__global__ void __launch_bounds__(256) skip_gemm(const float* __restrict__ sW) {
    __shared__ float As[GBK][GBM + 4];
    __shared__ float Bs[GBK][GBN + 4];
    int tid = threadIdx.x;
    int bm = blockIdx.x * GBM, bn = blockIdx.y * GBN;
    int ty = tid >> 4, tx = tid & 15;
    float acc[8][4];
    #pragma unroll
    for (int i = 0; i < 8; i++)
        #pragma unroll
        for (int j = 0; j < 4; j++) acc[i][j] = 0.f;

    for (int k0 = 0; k0 < 256; k0 += GBK) {
        #pragma unroll
        for (int qi = 0; qi < 2; qi++) {
            int q = tid + qi * 256;
            int row = q >> 2;
            int kq = (q & 3) * 4;
            int grow = bm + row;
            float4 a = make_float4(0.f, 0.f, 0.f, 0.f);
            if (grow < NN) a = *(const float4*)(g_hlast + (size_t)grow * 256 + k0 + kq);
            As[kq + 0][row] = a.x; As[kq + 1][row] = a.y;
            As[kq + 2][row] = a.z; As[kq + 3][row] = a.w;
        }
        {
            int q = tid;
            int j = q >> 2;
            int kq = (q & 3) * 4;
            int k = k0 + kq;
            int l = k >> 5, c = k & 31;
            float4 w = *(const float4*)(sW + l * 8192 + (bn + j) * 32 + c);
            Bs[kq + 0][j] = w.x; Bs[kq + 1][j] = w.y;
            Bs[kq + 2][j] = w.z; Bs[kq + 3][j] = w.w;
        }
        __syncthreads();
        #pragma unroll
        for (int k = 0; k < GBK; k++) {
            float4 alo = *(float4*)&As[k][ty * 8];
            float4 ahi = *(float4*)&As[k][ty * 8 + 4];
            float4 b = *(float4*)&Bs[k][tx * 4];
            float av[8] = {alo.x, alo.y, alo.z, alo.w, ahi.x, ahi.y, ahi.z, ahi.w};
            float bv[4] = {b.x, b.y, b.z, b.w};
            #pragma unroll
            for (int i = 0; i < 8; i++)
                #pragma unroll
                for (int j = 0; j < 4; j++) acc[i][j] += av[i] * bv[j];
        }
        __syncthreads();
    }
    float4 bb = *(const float4*)&g_sbsum[bn + tx * 4];
    #pragma unroll
    for (int i = 0; i < 8; i++) {
        int grow = bm + ty * 8 + i;
        if (grow < NN) {
            float4 o;
            o.x = fmaxf(acc[i][0] + bb.x, 0.f);
            o.y = fmaxf(acc[i][1] + bb.y, 0.f);
            o.z = fmaxf(acc[i][2] + bb.z, 0.f);
            o.w = fmaxf(acc[i][3] + bb.w, 0.f);
            *(float4*)&g_skip[(size_t)grow * 256 + bn + tx * 4] = o;
        }
    }
}

// g_y = g_skip[N,256] @ W^T + b ; W [512,256] row-major
__global__ void __launch_bounds__(256) end1_gemm2(const float* __restrict__ W,
                                                  const float* __restrict__ bias) {
    __shared__ float As[GBK][GBM + 4];
    __shared__ float Bs[GBK][GBN + 4];
    int tid = threadIdx.x;
    int bm = blockIdx.x * GBM, bn = blockIdx.y * GBN;
    int ty = tid >> 4, tx = tid & 15;
    float acc[8][4];
    #pragma unroll
    for (int i = 0; i < 8; i++)
        #pragma unroll
        for (int j = 0; j < 4; j++) acc[i][j] = 0.f;

    for (int k0 = 0; k0 < 256; k0 += GBK) {
        #pragma unroll
        for (int qi = 0; qi < 2; qi++) {
            int q = tid + qi * 256;
            int row = q >> 2;
            int kq = (q & 3) * 4;
            int grow = bm + row;
            float4 a = make_float4(0.f, 0.f, 0.f, 0.f);
            if (grow < NN) a = *(const float4*)(g_skip + (size_t)grow * 256 + k0 + kq);
            As[kq + 0][row] = a.x; As[kq + 1][row] = a.y;
            As[kq + 2][row] = a.z; As[kq + 3][row] = a.w;
        }
        {
            int q = tid;
            int j = q >> 2;
            int kq = (q & 3) * 4;
            float4 w = *(const float4*)(W + (size_t)(bn + j) * 256 + k0 + kq);
            Bs[kq + 0][j] = w.x; Bs[kq + 1][j] = w.y;
            Bs[kq + 2][j] = w.z; Bs[kq + 3][j] = w.w;
        }
        __syncthreads();
        #pragma unroll
        for (int k = 0; k < GBK; k++) {
            float4 alo = *(float4*)&As[k][ty * 8];
            float4 ahi = *(float4*)&As[k][ty * 8 + 4];
            float4 b = *(float4*)&Bs[k][tx * 4];
            float av[8] = {alo.x, alo.y, alo.z, alo.w, ahi.x, ahi.y, ahi.z, ahi.w};
            float bv[4] = {b.x, b.y, b.z, b.w};
            #pragma unroll
            for (int i = 0; i < 8; i++)
                #pragma unroll
                for (int j = 0; j < 4; j++) acc[i][j] += av[i] * bv[j];
        }
        __syncthreads();
    }
    float4 bb = *(const float4*)&bias[bn + tx * 4];
    #pragma unroll
    for (int i = 0; i < 8; i++) {
        int grow = bm + ty * 8 + i;
        if (grow < NN) {
            float4 o;
            o.x = acc[i][0] + bb.x; o.y = acc[i][1] + bb.y;
            o.z = acc[i][2] + bb.z; o.w = acc[i][3] + bb.w;
            *(float4*)&g_y[(size_t)grow * 512 + bn + tx * 4] = o;
        }
    }
}

// out = (g_y @ W2^T + b2) * stdev + means ; W2 [12,512]
__global__ void end2_final(const float* __restrict__ W, const float* __restrict__ bias,
                           float* __restrict__ out) {
    __shared__ float ws[512 * 12];
    __shared__ float bs[12];
    int tid = threadIdx.x;
    for (int i = tid; i < 6144; i += 256) {
        int c = i & 511, h = i >> 9;
        ws[c * 12 + h] = W[h * 512 + c];
    }
    if (tid < 12) bs[tid] = bias[tid];
    __syncthreads();

    int warp = tid >> 5, lane = tid & 31;
    int gw = blockIdx.x * 8 + warp;
    int nwarp = gridDim.x * 8;
    for (int n = gw; n < NN; n += nwarp) {
        float acc[12];
        #pragma unroll
        for (int h = 0; h < 12; h++) acc[h] = 0.f;
        #pragma unroll 4
        for (int i = 0; i < 16; i++) {
            int c = lane + 32 * i;
            float yv = g_y[(long)n * 512 + c];
            #pragma unroll
            for (int h = 0; h < 12; h++) acc[h] += yv * ws[c * 12 + h];
        }
        #pragma unroll
        for (int h = 0; h < 12; h++) {
            #pragma unroll
            for (int off = 16; off; off >>= 1)
                acc[h] += __shfl_down_sync(0xffffffffu, acc[h], off);
        }
        if (lane == 0) {
            float sd = g_stdev[n], mn = g_means[n];
            #pragma unroll
            for (int h = 0; h < 12; h++)
                out[n * 12 + h] = (acc[h] + bs[h]) * sd + mn;
        }
    }
}

extern "C" void kernel_launch(void* const* d_in, const int* in_sizes, int n_in,
                              void* d_out, int out_size) {
    (void)in_sizes; (void)n_in; (void)out_size;
    const float* x      = (const float*)d_in[0];
    const int*   ei     = (const int*)d_in[1];
    const float* ea     = (const float*)d_in[2];
    const float* startW = (const float*)d_in[3];
    const float* startb = (const float*)d_in[4];
    const float* fW     = (const float*)d_in[5];
    const float* fb     = (const float*)d_in[6];
    const float* gW     = (const float*)d_in[7];
    const float* gb     = (const float*)d_in[8];
    const float* sW     = (const float*)d_in[9];
    const float* sb     = (const float*)d_in[10];
    const float* g0W0   = (const float*)d_in[11];
    const float* g0W1   = (const float*)d_in[12];
    const float* g0b    = (const float*)d_in[13];
    const float* g1W0   = (const float*)d_in[14];
    const float* g1W1   = (const float*)d_in[15];
    const float* g1b    = (const float*)d_in[16];
    const float* e1W    = (const float*)d_in[17];
    const float* e1b    = (const float*)d_in[18];
    const float* e2W    = (const float*)d_in[19];
    const float* e2b    = (const float*)d_in[20];
    float* out = (float*)d_out;

    float *hA, *hB, *tx1;
    cudaGetSymbolAddress((void**)&hA, g_hA);
    cudaGetSymbolAddress((void**)&hB, g_hB);
    cudaGetSymbolAddress((void**)&tx1, g_tx1);

    zero_prep<<<(NN + 255) / 256, 256>>>(sb);
    deg_kernel<<<(NE + 255) / 256, 256>>>(ei, ea);
    dinv_kernel<<<(NN + 255) / 256, 256>>>();
    norme_kernel<<<(NE + 255) / 256, 256>>>(ei, ea);
    instnorm_start<<<2500, 256>>>(x, startW, startb);

    // layer 0: 13 -> 12, d=1 (hA -> hB), no fold
    conv_kernel<0, 13, 12, 1, -1, true><<<625, 256>>>(hA, hB, fW, fb, gW, gb);
    bn_finalize<0, 12, 0><<<1, 32>>>();

    // GCN0 on [N,384] (fold BN0 into gathers; hB -> hA)
    cudaMemsetAsync(tx1, 0, (size_t)NN * 384 * sizeof(float));
    scatter_kernel<384, 12, 0><<<(NE * 96 + 255) / 256, 256>>>(ei, hB);
    cheb_gemm2<384, 12, 0><<<dim3(157, 6), 256>>>(hB, tx1, g0W0, g0W1, g0b, hA);

    // layer 1: 12 -> 10, d=2 (hA -> hB), input = GCN output, no fold
    conv_kernel<1, 12, 10, 2, -1, true><<<625, 256>>>(hA, hB, fW, fb, gW, gb);
    // layer 2: 10 -> 9, d=1 (hB -> hA), fold BN1
    conv_kernel<2, 10, 9, 1, 1, true><<<625, 256>>>(hB, hA, fW, fb, gW, gb);
    // layer 3: 9 -> 7, d=2 (hA -> hB), fold BN2
    conv_kernel<3, 9, 7, 2, 2, true><<<625, 256>>>(hA, hB, fW, fb, gW, gb);
    // layer 4: 7 -> 6, d=1 (hB -> hA), fold BN3
    conv_kernel<4, 7, 6, 1, 3, true><<<625, 256>>>(hB, hA, fW, fb, gW, gb);
    bn_finalize<4, 6, 1><<<1, 32>>>();

    // GCN1 on [N,192] (fold BN4; hA -> hB)
    cudaMemsetAsync(tx1, 0, (size_t)NN * 192 * sizeof(float));
    scatter_kernel<192, 6, 1><<<(NE * 48 + 255) / 256, 256>>>(ei, hA);
    cheb_gemm2<192, 6, 1><<<dim3(157, 3), 256>>>(hA, tx1, g1W0, g1W1, g1b, hB);

    // layer 5: 6 -> 4, d=2 (hB -> hA), input = GCN output, no fold
    conv_kernel<5, 6, 4, 2, -1, true><<<625, 256>>>(hB, hA, fW, fb, gW, gb);
    // layer 6: 4 -> 3, d=1 (hA -> hB), fold BN5
    conv_kernel<6, 4, 3, 1, 5, true><<<625, 256>>>(hA, hB, fW, fb, gW, gb);
    // layer 7: 3 -> 1, d=2 (hB -> unused), fold BN6, only hlast needed
    conv_kernel<7, 3, 1, 2, 6, false><<<625, 256>>>(hB, hA, fW, fb, gW, gb);

    // head: skip (all 8 layers in one GEMM, relu fused) -> end1 -> end2+denorm
    skip_gemm<<<dim3(157, 4), 256>>>(sW);
    end1_gemm2<<<dim3(157, 8), 256>>>(e1W, e1b);
    end2_final<<<2500, 256>>>(e2W, e2b, out);
}

// round 4
// speedup vs baseline: 1.5302x; 1.2109x over previous
#include <cuda_runtime.h>
#include <math.h>

#define NN 20000
#define NE 200000

typedef unsigned long long u64;

__device__ float g_hA[NN * 32 * 13];
__device__ float g_hB[NN * 32 * 13];
__device__ float g_tx1[NN * 384];
__device__ float g_hlast[NN * 256];
__device__ float g_skip[NN * 256];
__device__ float g_y[NN * 512];
__device__ float g_means[NN];
__device__ float g_stdev[NN];
__device__ float g_dinv[NN];
__device__ float g_norme[NE];
__device__ float g_bn[8 * 64];
__device__ float g_bnp[2 * 64];
__device__ float g_sbsum[256];

__device__ __forceinline__ u64 pk2(float lo, float hi) {
    u64 r; asm("mov.b64 %0, {%1, %2};" : "=l"(r) : "f"(lo), "f"(hi)); return r;
}
__device__ __forceinline__ void fma2(u64& d, u64 a, u64 b) {
    asm("fma.rn.f32x2 %0, %1, %2, %3;" : "=l"(d) : "l"(a), "l"(b), "l"(d));
}
__device__ __forceinline__ void upk2(float& lo, float& hi, u64 v) {
    asm("mov.b64 {%0, %1}, %2;" : "=f"(lo), "=f"(hi) : "l"(v));
}

__device__ __forceinline__ float ftanh(float x) {
    x = fminf(fmaxf(x, -15.f), 15.f);
    float e = __expf(2.f * x);
    return __fdividef(e - 1.f, e + 1.f);
}
__device__ __forceinline__ float fsig(float x) {
    x = fminf(fmaxf(x, -30.f), 30.f);
    return __fdividef(1.f, 1.f + __expf(-x));
}

__global__ void zero_prep(const float* __restrict__ sB) {
    int i = blockIdx.x * blockDim.x + threadIdx.x;
    if (i < 512) g_bn[i] = 0.f;
    if (i < NN) g_dinv[i] = 0.f;
    if (i < 256) {
        float s = 0.f;
        #pragma unroll
        for (int l = 0; l < 8; l++) s += sB[l * 256 + i];
        g_sbsum[i] = s;
    }
}
__global__ void deg_kernel(const int* __restrict__ ei, const float* __restrict__ ea) {
    int e = blockIdx.x * blockDim.x + threadIdx.x;
    if (e >= NE) return;
    int r = ei[e], c = ei[NE + e];
    float w = (r == c) ? 0.f : ea[e];
    if (w != 0.f) atomicAdd(&g_dinv[r], w);
}
__global__ void dinv_kernel() {
    int n = blockIdx.x * blockDim.x + threadIdx.x;
    if (n >= NN) return;
    float d = g_dinv[n];
    g_dinv[n] = (d > 0.f) ? rsqrtf(d) : 0.f;
}
__global__ void norme_kernel(const int* __restrict__ ei, const float* __restrict__ ea) {
    int e = blockIdx.x * blockDim.x + threadIdx.x;
    if (e >= NE) return;
    int r = ei[e], c = ei[NE + e];
    float w = (r == c) ? 0.f : ea[e];
    g_norme[e] = -g_dinv[r] * w * g_dinv[c];   // pre-negated
}

// instance norm over T + 1x1 start conv -> g_hA [N,32,13]
__global__ void instnorm_start(const float* __restrict__ x,
                               const float* __restrict__ sW,
                               const float* __restrict__ sb) {
    int gw = blockIdx.x * 8 + (threadIdx.x >> 5);
    int lane = threadIdx.x & 31;
    if (gw >= NN) return;
    float v = (lane < 13) ? x[gw * 13 + lane] : 0.f;
    float s = v;
    #pragma unroll
    for (int o = 16; o; o >>= 1) s += __shfl_xor_sync(0xffffffffu, s, o);
    float mean = s * (1.f / 13.f);
    float xc = (lane < 13) ? (v - mean) : 0.f;
    float q = xc * xc;
    #pragma unroll
    for (int o = 16; o; o >>= 1) q += __shfl_xor_sync(0xffffffffu, q, o);
    float sd = sqrtf(q * (1.f / 13.f) + 1e-5f);
    if (lane == 0) { g_means[gw] = mean; g_stdev[gw] = sd; }
    float nv = xc * __fdividef(1.f, sd);
    float w = sW[lane], b = sb[lane];
    float* hr = g_hA + (gw * 32 + lane) * 13;
    #pragma unroll
    for (int t = 0; t < 13; t++)
        hr[t] = w * __shfl_sync(0xffffffffu, nv, t) + b;
}

// fused: [BN-fold of prev layer on load] + dilated conv + tanh*sig + residual
// + BN stats + hlast capture
template <int L, int TIN, int TOUT, int DIL, int PREVL, bool WRITE_Y>
__global__ void conv_kernel(const float* __restrict__ X, float* __restrict__ Y,
                            const float* __restrict__ fW, const float* __restrict__ fB,
                            const float* __restrict__ gW, const float* __restrict__ gB) {
    __shared__ float wf0[32 * 33], wf1[32 * 33], wg0[32 * 33], wg1[32 * 33];
    __shared__ float bfs[32], bgs[32];
    __shared__ float bsc[32], bsh[32];
    __shared__ float hs[8][32 * TIN];
    __shared__ float bnred[64];
    int tid = threadIdx.x;
    for (int i = tid; i < 1024; i += 256) {
        int c = i & 31, o = i >> 5;
        int gbase = (L * 32 + o) * 64 + c * 2;
        wf0[c * 33 + o] = fW[gbase + 0];
        wf1[c * 33 + o] = fW[gbase + 1];
        wg0[c * 33 + o] = gW[gbase + 0];
        wg1[c * 33 + o] = gW[gbase + 1];
    }
    if (tid < 32) {
        bfs[tid] = fB[L * 32 + tid]; bgs[tid] = gB[L * 32 + tid];
        if (PREVL >= 0) {
            const float cnt = (float)NN * (float)TIN;
            float m = g_bn[PREVL * 64 + tid] / cnt;
            float var = fmaxf(g_bn[PREVL * 64 + 32 + tid] / cnt - m * m, 0.f);
            float s = rsqrtf(var + 1e-5f);
            bsc[tid] = s; bsh[tid] = -m * s;
        }
    }
    if (tid < 64) bnred[tid] = 0.f;
    __syncthreads();

    int warp = tid >> 5, lane = tid & 31;
    int gw = blockIdx.x * 8 + warp;
    int nwarp = gridDim.x * 8;
    float bsum = 0.f, bsq = 0.f;
    float* hwp = &hs[warp][0];

    for (int n = gw; n < NN; n += nwarp) {
        const float* xr = X + (n * 32 + lane) * TIN;
        float* hrow = hwp + lane * TIN;
        #pragma unroll
        for (int t = 0; t < TIN; t++) {
            float v = xr[t];
            if (PREVL >= 0) v = v * bsc[lane] + bsh[lane];
            hrow[t] = v;
        }
        __syncwarp();

        float accf[TOUT], accg[TOUT];
        #pragma unroll
        for (int t = 0; t < TOUT; t++) { accf[t] = bfs[lane]; accg[t] = bgs[lane]; }

        #pragma unroll 4
        for (int c = 0; c < 32; c++) {
            float w00 = wf0[c * 33 + lane], w01 = wf1[c * 33 + lane];
            float w10 = wg0[c * 33 + lane], w11 = wg1[c * 33 + lane];
            const float* hv = hwp + c * TIN;
            float hvr[TIN];
            #pragma unroll
            for (int t = 0; t < TIN; t++) hvr[t] = hv[t];
            #pragma unroll
            for (int t = 0; t < TOUT; t++) {
                accf[t] += w00 * hvr[t] + w01 * hvr[t + DIL];
                accg[t] += w10 * hvr[t] + w11 * hvr[t + DIL];
            }
        }
        float* yr = Y + (n * 32 + lane) * TOUT;
        #pragma unroll
        for (int t = 0; t < TOUT; t++) {
            float f = ftanh(accf[t]);
            float g = fsig(accg[t]);
            float hn = f * g;
            if (t == TOUT - 1) g_hlast[n * 256 + L * 32 + lane] = hn;
            if (WRITE_Y) {
                float ho = hn + hwp[lane * TIN + t + DIL];
                yr[t] = ho;
                bsum += ho; bsq += ho * ho;
            }
        }
        __syncwarp();
    }
    if (WRITE_Y) {
        atomicAdd(&bnred[lane], bsum);
        atomicAdd(&bnred[32 + lane], bsq);
        __syncthreads();
        if (tid < 64) atomicAdd(&g_bn[L * 64 + tid], bnred[tid]);
    }
}

template <int L, int TOUT, int SLOT>
__global__ void bn_finalize() {
    int i = threadIdx.x;
    if (i >= 32) return;
    const float cnt = (float)NN * (float)TOUT;
    float m = g_bn[L * 64 + i] / cnt;
    float var = fmaxf(g_bn[L * 64 + 32 + i] / cnt - m * m, 0.f);
    float s = rsqrtf(var + 1e-5f);
    g_bnp[SLOT * 64 + i] = s;
    g_bnp[SLOT * 64 + 32 + i] = -m * s;
}

// tx1[col] += (-norm) * BNfold(xf[row])  -- vector red
template <int F, int TDIV, int SLOT>
__global__ void scatter_kernel(const int* __restrict__ ei, const float* __restrict__ xf) {
    const int CH = F / 4;
    long gid = (long)blockIdx.x * blockDim.x + threadIdx.x;
    if (gid >= (long)NE * CH) return;
    int e = (int)(gid / CH);
    int q = (int)(gid - (long)e * CH);
    float nrm = g_norme[e];
    if (nrm == 0.f) return;
    int r = ei[e], c = ei[NE + e];
    float4 v = *(const float4*)(xf + (long)r * F + q * 4);
    const float* bp = g_bnp + SLOT * 64;
    int k = q * 4;
    int c0 = k / TDIV, c1 = (k + 1) / TDIV, c2 = (k + 2) / TDIV, c3 = (k + 3) / TDIV;
    float ox = nrm * (v.x * bp[c0] + bp[32 + c0]);
    float oy = nrm * (v.y * bp[c1] + bp[32 + c1]);
    float oz = nrm * (v.z * bp[c2] + bp[32 + c2]);
    float ow = nrm * (v.w * bp[c3] + bp[32 + c3]);
    float* dst = g_tx1 + (long)c * F + q * 4;
    asm volatile("red.global.add.v4.f32 [%0], {%1, %2, %3, %4};"
                 :: "l"(dst), "f"(ox), "f"(oy), "f"(oz), "f"(ow) : "memory");
}

// ===== GEMM family: BM=128 BN=64 BK=16, 256 threads, 8x4 per thread, f32x2 =====
#define GBM 128
#define GBN 64
#define GBK 16

// C = BNfold(A1)@B1 + A2@B2 + bias
template <int F, int TDIV, int SLOT>
__global__ void __launch_bounds__(256) cheb_gemm2(
        const float* __restrict__ A1, const float* __restrict__ A2,
        const float* __restrict__ B1, const float* __restrict__ B2,
        const float* __restrict__ bias, float* __restrict__ C) {
    __shared__ float As1[GBK][GBM + 4], As2[GBK][GBM + 4];
    __shared__ float Bs1[GBK][GBN], Bs2[GBK][GBN];
    __shared__ float bsc[32], bsh[32];
    int tid = threadIdx.x;
    if (tid < 32) { bsc[tid] = g_bnp[SLOT * 64 + tid]; bsh[tid] = g_bnp[SLOT * 64 + 32 + tid]; }
    __syncthreads();
    int bm = blockIdx.x * GBM, bn = blockIdx.y * GBN;
    int ty = tid >> 4, tx = tid & 15;
    u64 acc2[4][4];   // (i-pair, j) : lo=acc[2p][j], hi=acc[2p+1][j]
    #pragma unroll
    for (int p = 0; p < 4; p++)
        #pragma unroll
        for (int j = 0; j < 4; j++) acc2[p][j] = 0ull;

    for (int k0 = 0; k0 < F; k0 += GBK) {
        #pragma unroll
        for (int qi = 0; qi < 2; qi++) {
            int q = tid + qi * 256;
            int row = q >> 2;
            int kq = (q & 3) * 4;
            int grow = bm + row;
            float4 a1 = make_float4(0.f, 0.f, 0.f, 0.f), a2 = a1;
            if (grow < NN) {
                a1 = *(const float4*)(A1 + (size_t)grow * F + k0 + kq);
                a2 = *(const float4*)(A2 + (size_t)grow * F + k0 + kq);
            }
            int k = k0 + kq;
            int c0 = k / TDIV, c1 = (k + 1) / TDIV, c2 = (k + 2) / TDIV, c3 = (k + 3) / TDIV;
            a1.x = a1.x * bsc[c0] + bsh[c0];
            a1.y = a1.y * bsc[c1] + bsh[c1];
            a1.z = a1.z * bsc[c2] + bsh[c2];
            a1.w = a1.w * bsc[c3] + bsh[c3];
            As1[kq + 0][row] = a1.x; As1[kq + 1][row] = a1.y;
            As1[kq + 2][row] = a1.z; As1[kq + 3][row] = a1.w;
            As2[kq + 0][row] = a2.x; As2[kq + 1][row] = a2.y;
            As2[kq + 2][row] = a2.z; As2[kq + 3][row] = a2.w;
        }
        {
            int kk = tid >> 4;
            int jb = (tid & 15) * 4;
            *(float4*)&Bs1[kk][jb] = *(const float4*)(B1 + (size_t)(k0 + kk) * F + bn + jb);
            *(float4*)&Bs2[kk][jb] = *(const float4*)(B2 + (size_t)(k0 + kk) * F + bn + jb);
        }
        __syncthreads();
        #pragma unroll
        for (int k = 0; k < GBK; k++) {
            ulonglong2 a1lo = *(ulonglong2*)&As1[k][ty * 8];
            ulonglong2 a1hi = *(ulonglong2*)&As1[k][ty * 8 + 4];
            ulonglong2 a2lo = *(ulonglong2*)&As2[k][ty * 8];
            ulonglong2 a2hi = *(ulonglong2*)&As2[k][ty * 8 + 4];
            u64 a1v[4] = {a1lo.x, a1lo.y, a1hi.x, a1hi.y};
            u64 a2v[4] = {a2lo.x, a2lo.y, a2hi.x, a2hi.y};
            float4 b1 = *(float4*)&Bs1[k][tx * 4];
            float4 b2 = *(float4*)&Bs2[k][tx * 4];
            u64 b1s[4] = {pk2(b1.x, b1.x), pk2(b1.y, b1.y), pk2(b1.z, b1.z), pk2(b1.w, b1.w)};
            u64 b2s[4] = {pk2(b2.x, b2.x), pk2(b2.y, b2.y), pk2(b2.z, b2.z), pk2(b2.w, b2.w)};
            #pragma unroll
            for (int p = 0; p < 4; p++)
                #pragma unroll
                for (int j = 0; j < 4; j++) {
                    fma2(acc2[p][j], a1v[p], b1s[j]);
                    fma2(acc2[p][j], a2v[p], b2s[j]);
                }
        }
        __syncthreads();
    }
    float4 bv = *(const float4*)&bias[bn + tx * 4];
    float bvv[4] = {bv.x, bv.y, bv.z, bv.w};
    #pragma unroll
    for (int p = 0; p < 4; p++) {
        float lo[4], hi[4];
        #pragma unroll
        for (int j = 0; j < 4; j++) upk2(lo[j], hi[j], acc2[p][j]);
        int r0 = bm + ty * 8 + 2 * p;
        if (r0 < NN) {
            float4 o = make_float4(lo[0] + bvv[0], lo[1] + bvv[1], lo[2] + bvv[2], lo[3] + bvv[3]);
            *(float4*)&C[(size_t)r0 * F + bn + tx * 4] = o;
        }
        if (r0 + 1 < NN) {
            float4 o = make_float4(hi[0] + bvv[0], hi[1] + bvv[1], hi[2] + bvv[2], hi[3] + bvv[3]);
            *(float4*)&C[(size_t)(r0 + 1) * F + bn + tx * 4] = o;
        }
    }
}

// generic single-A GEMM body (f32x2) used by skip_gemm and end1_gemm2
// OUTF: output row stride; RELU on store; bias pointer
template <int OUTF, bool RELU>
__device__ __forceinline__ void gemm1_body(
        const float* __restrict__ Asrc, int asrcF,
        const float* __restrict__ bias, float* __restrict__ Cdst,
        float (*loadB)(const float*, int, int, int), const float* Wp) {
    // unused generic path (kept simple below instead)
}

// g_skip = relu( g_hlast[N,256] @ Wcat^T + sbsum )
__global__ void __launch_bounds__(256) skip_gemm(const float* __restrict__ sW) {
    __shared__ float As[GBK][GBM + 4];
    __shared__ float Bs[GBK][GBN + 4];
    int tid = threadIdx.x;
    int bm = blockIdx.x * GBM, bn = blockIdx.y * GBN;
    int ty = tid >> 4, tx = tid & 15;
    u64 acc2[4][4];
    #pragma unroll
    for (int p = 0; p < 4; p++)
        #pragma unroll
        for (int j = 0; j < 4; j++) acc2[p][j] = 0ull;

    for (int k0 = 0; k0 < 256; k0 += GBK) {
        #pragma unroll
        for (int qi = 0; qi < 2; qi++) {
            int q = tid + qi * 256;
            int row = q >> 2;
            int kq = (q & 3) * 4;
            int grow = bm + row;
            float4 a = make_float4(0.f, 0.f, 0.f, 0.f);
            if (grow < NN) a = *(const float4*)(g_hlast + (size_t)grow * 256 + k0 + kq);
            As[kq + 0][row] = a.x; As[kq + 1][row] = a.y;
            As[kq + 2][row] = a.z; As[kq + 3][row] = a.w;
        }
        {
            int j = tid >> 2;
            int kq = (tid & 3) * 4;
            int k = k0 + kq;
            int l = k >> 5, c = k & 31;
            float4 w = *(const float4*)(sW + l * 8192 + (bn + j) * 32 + c);
            Bs[kq + 0][j] = w.x; Bs[kq + 1][j] = w.y;
            Bs[kq + 2][j] = w.z; Bs[kq + 3][j] = w.w;
        }
        __syncthreads();
        #pragma unroll
        for (int k = 0; k < GBK; k++) {
            ulonglong2 alo = *(ulonglong2*)&As[k][ty * 8];
            ulonglong2 ahi = *(ulonglong2*)&As[k][ty * 8 + 4];
            u64 av[4] = {alo.x, alo.y, ahi.x, ahi.y};
            float4 b = *(float4*)&Bs[k][tx * 4];
            u64 bs2[4] = {pk2(b.x, b.x), pk2(b.y, b.y), pk2(b.z, b.z), pk2(b.w, b.w)};
            #pragma unroll
            for (int p = 0; p < 4; p++)
                #pragma unroll
                for (int j = 0; j < 4; j++) fma2(acc2[p][j], av[p], bs2[j]);
        }
        __syncthreads();
    }
    float4 bb = *(const float4*)&g_sbsum[bn + tx * 4];
    float bvv[4] = {bb.x, bb.y, bb.z, bb.w};
    #pragma unroll
    for (int p = 0; p < 4; p++) {
        float lo[4], hi[4];
        #pragma unroll
        for (int j = 0; j < 4; j++) upk2(lo[j], hi[j], acc2[p][j]);
        int r0 = bm + ty * 8 + 2 * p;
        if (r0 < NN) {
            float4 o = make_float4(fmaxf(lo[0] + bvv[0], 0.f), fmaxf(lo[1] + bvv[1], 0.f),
                                   fmaxf(lo[2] + bvv[2], 0.f), fmaxf(lo[3] + bvv[3], 0.f));
            *(float4*)&g_skip[(size_t)r0 * 256 + bn + tx * 4] = o;
        }
        if (r0 + 1 < NN) {
            float4 o = make_float4(fmaxf(hi[0] + bvv[0], 0.f), fmaxf(hi[1] + bvv[1], 0.f),
                                   fmaxf(hi[2] + bvv[2], 0.f), fmaxf(hi[3] + bvv[3], 0.f));
            *(float4*)&g_skip[(size_t)(r0 + 1) * 256 + bn + tx * 4] = o;
        }
    }
}

// g_y = g_skip[N,256] @ W^T + b ; W [512,256]
__global__ void __launch_bounds__(256) end1_gemm2(const float* __restrict__ W,
                                                  const float* __restrict__ bias) {
    __shared__ float As[GBK][GBM + 4];
    __shared__ float Bs[GBK][GBN + 4];
    int tid = threadIdx.x;
    int bm = blockIdx.x * GBM, bn = blockIdx.y * GBN;
    int ty = tid >> 4, tx = tid & 15;
    u64 acc2[4][4];
    #pragma unroll
    for (int p = 0; p < 4; p++)
        #pragma unroll
        for (int j = 0; j < 4; j++) acc2[p][j] = 0ull;

    for (int k0 = 0; k0 < 256; k0 += GBK) {
        #pragma unroll
        for (int qi = 0; qi < 2; qi++) {
            int q = tid + qi * 256;
            int row = q >> 2;
            int kq = (q & 3) * 4;
            int grow = bm + row;
            float4 a = make_float4(0.f, 0.f, 0.f, 0.f);
            if (grow < NN) a = *(const float4*)(g_skip + (size_t)grow * 256 + k0 + kq);
            As[kq + 0][row] = a.x; As[kq + 1][row] = a.y;
            As[kq + 2][row] = a.z; As[kq + 3][row] = a.w;
        }
        {
            int j = tid >> 2;
            int kq = (tid & 3) * 4;
            float4 w = *(const float4*)(W + (size_t)(bn + j) * 256 + k0 + kq);
            Bs[kq + 0][j] = w.x; Bs[kq + 1][j] = w.y;
            Bs[kq + 2][j] = w.z; Bs[kq + 3][j] = w.w;
        }
        __syncthreads();
        #pragma unroll
        for (int k = 0; k < GBK; k++) {
            ulonglong2 alo = *(ulonglong2*)&As[k][ty * 8];
            ulonglong2 ahi = *(ulonglong2*)&As[k][ty * 8 + 4];
            u64 av[4] = {alo.x, alo.y, ahi.x, ahi.y};
            float4 b = *(float4*)&Bs[k][tx * 4];
            u64 bs2[4] = {pk2(b.x, b.x), pk2(b.y, b.y), pk2(b.z, b.z), pk2(b.w, b.w)};
            #pragma unroll
            for (int p = 0; p < 4; p++)
                #pragma unroll
                for (int j = 0; j < 4; j++) fma2(acc2[p][j], av[p], bs2[j]);
        }
        __syncthreads();
    }
    float4 bb = *(const float4*)&bias[bn + tx * 4];
    float bvv[4] = {bb.x, bb.y, bb.z, bb.w};
    #pragma unroll
    for (int p = 0; p < 4; p++) {
        float lo[4], hi[4];
        #pragma unroll
        for (int j = 0; j < 4; j++) upk2(lo[j], hi[j], acc2[p][j]);
        int r0 = bm + ty * 8 + 2 * p;
        if (r0 < NN) {
            float4 o = make_float4(lo[0] + bvv[0], lo[1] + bvv[1], lo[2] + bvv[2], lo[3] + bvv[3]);
            *(float4*)&g_y[(size_t)r0 * 512 + bn + tx * 4] = o;
        }
        if (r0 + 1 < NN) {
            float4 o = make_float4(hi[0] + bvv[0], hi[1] + bvv[1], hi[2] + bvv[2], hi[3] + bvv[3]);
            *(float4*)&g_y[(size_t)(r0 + 1) * 512 + bn + tx * 4] = o;
        }
    }
}

// out = (g_y @ W2^T + b2) * stdev + means ; W2 [12,512]
__global__ void end2_final(const float* __restrict__ W, const float* __restrict__ bias,
                           float* __restrict__ out) {
    __shared__ float ws[512 * 12];
    __shared__ float bs[12];
    int tid = threadIdx.x;
    for (int i = tid; i < 6144; i += 256) {
        int c = i & 511, h = i >> 9;
        ws[c * 12 + h] = W[h * 512 + c];
    }
    if (tid < 12) bs[tid] = bias[tid];
    __syncthreads();

    int warp = tid >> 5, lane = tid & 31;
    int gw = blockIdx.x * 8 + warp;
    int nwarp = gridDim.x * 8;
    for (int n = gw; n < NN; n += nwarp) {
        float acc[12];
        #pragma unroll
        for (int h = 0; h < 12; h++) acc[h] = 0.f;
        #pragma unroll 4
        for (int i = 0; i < 16; i++) {
            int c = lane + 32 * i;
            float yv = g_y[(long)n * 512 + c];
            #pragma unroll
            for (int h = 0; h < 12; h++) acc[h] += yv * ws[c * 12 + h];
        }
        #pragma unroll
        for (int h = 0; h < 12; h++) {
            #pragma unroll
            for (int off = 16; off; off >>= 1)
                acc[h] += __shfl_down_sync(0xffffffffu, acc[h], off);
        }
        if (lane == 0) {
            float sd = g_stdev[n], mn = g_means[n];
            #pragma unroll
            for (int h = 0; h < 12; h++)
                out[n * 12 + h] = (acc[h] + bs[h]) * sd + mn;
        }
    }
}

extern "C" void kernel_launch(void* const* d_in, const int* in_sizes, int n_in,
                              void* d_out, int out_size) {
    (void)in_sizes; (void)n_in; (void)out_size;
    const float* x      = (const float*)d_in[0];
    const int*   ei     = (const int*)d_in[1];
    const float* ea     = (const float*)d_in[2];
    const float* startW = (const float*)d_in[3];
    const float* startb = (const float*)d_in[4];
    const float* fW     = (const float*)d_in[5];
    const float* fb     = (const float*)d_in[6];
    const float* gW     = (const float*)d_in[7];
    const float* gb     = (const float*)d_in[8];
    const float* sW     = (const float*)d_in[9];
    const float* sb     = (const float*)d_in[10];
    const float* g0W0   = (const float*)d_in[11];
    const float* g0W1   = (const float*)d_in[12];
    const float* g0b    = (const float*)d_in[13];
    const float* g1W0   = (const float*)d_in[14];
    const float* g1W1   = (const float*)d_in[15];
    const float* g1b    = (const float*)d_in[16];
    const float* e1W    = (const float*)d_in[17];
    const float* e1b    = (const float*)d_in[18];
    const float* e2W    = (const float*)d_in[19];
    const float* e2b    = (const float*)d_in[20];
    float* out = (float*)d_out;

    float *hA, *hB, *tx1;
    cudaGetSymbolAddress((void**)&hA, g_hA);
    cudaGetSymbolAddress((void**)&hB, g_hB);
    cudaGetSymbolAddress((void**)&tx1, g_tx1);

    zero_prep<<<(NN + 255) / 256, 256>>>(sb);
    deg_kernel<<<(NE + 255) / 256, 256>>>(ei, ea);
    dinv_kernel<<<(NN + 255) / 256, 256>>>();
    norme_kernel<<<(NE + 255) / 256, 256>>>(ei, ea);
    instnorm_start<<<2500, 256>>>(x, startW, startb);

    // layer 0: 13 -> 12, d=1 (hA -> hB)
    conv_kernel<0, 13, 12, 1, -1, true><<<625, 256>>>(hA, hB, fW, fb, gW, gb);
    bn_finalize<0, 12, 0><<<1, 32>>>();

    // GCN0 on [N,384] (fold BN0; hB -> hA)
    cudaMemsetAsync(tx1, 0, (size_t)NN * 384 * sizeof(float));
    scatter_kernel<384, 12, 0><<<(NE * 96 + 255) / 256, 256>>>(ei, hB);
    cheb_gemm2<384, 12, 0><<<dim3(157, 6), 256>>>(hB, tx1, g0W0, g0W1, g0b, hA);

    // layer 1: 12 -> 10, d=2 (hA -> hB)
    conv_kernel<1, 12, 10, 2, -1, true><<<625, 256>>>(hA, hB, fW, fb, gW, gb);
    // layer 2: 10 -> 9, d=1 (hB -> hA), fold BN1
    conv_kernel<2, 10, 9, 1, 1, true><<<625, 256>>>(hB, hA, fW, fb, gW, gb);
    // layer 3: 9 -> 7, d=2 (hA -> hB), fold BN2
    conv_kernel<3, 9, 7, 2, 2, true><<<625, 256>>>(hA, hB, fW, fb, gW, gb);
    // layer 4: 7 -> 6, d=1 (hB -> hA), fold BN3
    conv_kernel<4, 7, 6, 1, 3, true><<<625, 256>>>(hB, hA, fW, fb, gW, gb);
    bn_finalize<4, 6, 1><<<1, 32>>>();

    // GCN1 on [N,192] (fold BN4; hA -> hB)
    cudaMemsetAsync(tx1, 0, (size_t)NN * 192 * sizeof(float));
    scatter_kernel<192, 6, 1><<<(NE * 48 + 255) / 256, 256>>>(ei, hA);
    cheb_gemm2<192, 6, 1><<<dim3(157, 3), 256>>>(hA, tx1, g1W0, g1W1, g1b, hB);

    // layer 5: 6 -> 4, d=2 (hB -> hA)
    conv_kernel<5, 6, 4, 2, -1, true><<<625, 256>>>(hB, hA, fW, fb, gW, gb);
    // layer 6: 4 -> 3, d=1 (hA -> hB), fold BN5
    conv_kernel<6, 4, 3, 1, 5, true><<<625, 256>>>(hA, hB, fW, fb, gW, gb);
    // layer 7: 3 -> 1, d=2, fold BN6, only hlast needed
    conv_kernel<7, 3, 1, 2, 6, false><<<625, 256>>>(hB, hA, fW, fb, gW, gb);

    // head
    skip_gemm<<<dim3(157, 4), 256>>>(sW);
    end1_gemm2<<<dim3(157, 8), 256>>>(e1W, e1b);
    end2_final<<<2500, 256>>>(e2W, e2b, out);
}